// round 12
// baseline (speedup 1.0000x reference)
#include <cuda_runtime.h>
#include <cuda_bf16.h>
#include <cuda_fp16.h>
#include <math.h>
#include <stdint.h>

// ---------------- problem constants ----------------
#define B_ 2
#define S_ 2048
#define D_ 2048
#define H_ 16
#define RK 512
#define ROPE_ 64
#define NOPE_ 128
#define QK_HD 192
#define V_HD 128
#define CD 576            // RK + ROPE
#define BS (B_ * S_)      // 4096
#define QROW (H_ * CD)    // 9216
#define QBROW (H_ * QK_HD)// 3072
#define OLROW (H_ * RK)   // 8192
#define OVROW (H_ * V_HD) // 2048
#define EPS_ 1.1920929e-07f
#define SCALE_ 0.0721687836487032f

// ---------------- scratch ----------------
__device__ float  g_q   [(size_t)BS * QBROW];      // raw fp32 q proj
__device__ float  g_kvt [(size_t)BS * CD];         // raw fp32 kv_a proj
__device__ __half g_qfh [(size_t)BS * H_ * CD];    // flash q (fp16)
__device__ __half g_kfh [(size_t)BS * CD];         // flash K (fp16)
__device__ __half g_kvT [(size_t)B_ * RK * S_];    // flash V transposed [b][d][s] fp16
__device__ float  g_ol  [(size_t)BS * OLROW];      // raw fp32 flash out
__device__ float  g_ov  [(size_t)BS * OVROW];      // raw fp32 v-up out

// ---------------- helpers ----------------
__device__ __forceinline__ void split_bf2(float2 p, uint32_t& hi, uint32_t& lo) {
    __nv_bfloat162 h = __float22bfloat162_rn(p);
    float hx = __low2float(h), hy = __high2float(h);
    __nv_bfloat162 l = __float22bfloat162_rn(make_float2(p.x - hx, p.y - hy));
    hi = *(uint32_t*)&h;
    lo = *(uint32_t*)&l;
}
__device__ __forceinline__ void mma_bf16(float c[4],
    uint32_t a0, uint32_t a1, uint32_t a2, uint32_t a3, uint32_t b0, uint32_t b1)
{
    asm volatile("mma.sync.aligned.m16n8k16.row.col.f32.bf16.bf16.f32 "
        "{%0,%1,%2,%3}, {%4,%5,%6,%7}, {%8,%9}, {%0,%1,%2,%3};\n"
        : "+f"(c[0]), "+f"(c[1]), "+f"(c[2]), "+f"(c[3])
        : "r"(a0), "r"(a1), "r"(a2), "r"(a3), "r"(b0), "r"(b1));
}
__device__ __forceinline__ void mma_f16(float c[4],
    uint32_t a0, uint32_t a1, uint32_t a2, uint32_t a3, uint32_t b0, uint32_t b1)
{
    asm volatile("mma.sync.aligned.m16n8k16.row.col.f32.f16.f16.f32 "
        "{%0,%1,%2,%3}, {%4,%5,%6,%7}, {%8,%9}, {%0,%1,%2,%3};\n"
        : "+f"(c[0]), "+f"(c[1]), "+f"(c[2]), "+f"(c[3])
        : "r"(a0), "r"(a1), "r"(a2), "r"(a3), "r"(b0), "r"(b1));
}
__device__ __forceinline__ uint32_t sm_u32(const void* p) {
    return (uint32_t)__cvta_generic_to_shared(p);
}
#define CPA16(d, s) asm volatile("cp.async.ca.shared.global [%0], [%1], 16;\n" :: "r"(d), "l"(s))
#define CPCOMMIT()  asm volatile("cp.async.commit_group;\n")
#define CPWAIT(n)   asm volatile("cp.async.wait_group %0;\n" :: "n"(n))

// ---------------- bf16-split pipelined GEMM (R6, unchanged math) ----------------
// C = alpha * A*op(B) (+bias). A:(M,K) rm raw fp32. TB ? B:(N,K) rm : B:(K,N) rm.
// 128x64x16 tile, 3-stage cp.async. OM: 0 = fp32 out, 1 = fp16 out.
#define GA_ST 3072            // 128 * 24 floats per A stage
#define GB_ST 1536            // max(64*24, 16*72)
#define GEMM_SMEM ((3 * (GA_ST + GB_ST)) * 4)   // 55296 B dynamic
template<bool TB, bool HASB, int OM>
__global__ __launch_bounds__(256)
void gemm_bs(int K,
             const float* __restrict__ A, int lda, long aB,
             const float* __restrict__ Bm, int ldb, long bB,
             void* Cv, int ldc, long cB,
             const float* __restrict__ bias, float alpha)
{
    extern __shared__ float gsm[];
    float* sA = gsm;                  // 3 stages, pitch 24
    float* sB = gsm + 3 * GA_ST;

    int z = blockIdx.z;
    A  += (long)z * aB;
    Bm += (long)z * bB;

    long m0 = (long)blockIdx.y * 128;
    long n0 = (long)blockIdx.x * 64;
    int tid = threadIdx.x;
    int w = tid >> 5, lane = tid & 31, gid = lane >> 2, tig = lane & 3;
    int wm = w & 3, wn = w >> 2;

    uint32_t sAu = sm_u32(sA), sBu = sm_u32(sB);
    int nk = K / 16;

    auto issue = [&](int s, int kt) {
        int k0 = kt * 16;
#pragma unroll
        for (int i = 0; i < 2; i++) {
            int c = tid + i * 256;
            int r = c >> 2, kq = (c & 3) * 4;
            CPA16(sAu + (s * GA_ST + r * 24 + kq) * 4,
                  &A[(m0 + r) * (long)lda + k0 + kq]);
        }
        if (TB) {
            int r = tid >> 2, kq = (tid & 3) * 4;
            CPA16(sBu + (s * GB_ST + r * 24 + kq) * 4,
                  &Bm[(n0 + r) * (long)ldb + k0 + kq]);
        } else {
            int kk = tid >> 4, nq = (tid & 15) * 4;
            CPA16(sBu + (s * GB_ST + kk * 72 + nq) * 4,
                  &Bm[(long)(k0 + kk) * (long)ldb + n0 + nq]);
        }
    };

    float acc[2][4][4];
#pragma unroll
    for (int mi = 0; mi < 2; mi++)
#pragma unroll
        for (int j = 0; j < 4; j++)
#pragma unroll
            for (int e = 0; e < 4; e++) acc[mi][j][e] = 0.f;

    issue(0, 0); CPCOMMIT();
    if (nk > 1) { issue(1, 1); CPCOMMIT(); }

    for (int kt = 0; kt < nk; kt++) {
        CPWAIT(1);
        __syncthreads();
        if (kt + 2 < nk) { issue((kt + 2) % 3, kt + 2); CPCOMMIT(); }

        const float* cA = sA + (kt % 3) * GA_ST;
        const float* cB = sB + (kt % 3) * GB_ST;

        uint32_t ahi[2][4], alo[2][4], bhi[4][2], blo[4][2];
#pragma unroll
        for (int mi = 0; mi < 2; mi++) {
            int rb = wm * 32 + mi * 16 + gid;
            split_bf2(*(const float2*)&cA[rb * 24 + 2 * tig],           ahi[mi][0], alo[mi][0]);
            split_bf2(*(const float2*)&cA[(rb + 8) * 24 + 2 * tig],     ahi[mi][1], alo[mi][1]);
            split_bf2(*(const float2*)&cA[rb * 24 + 2 * tig + 8],       ahi[mi][2], alo[mi][2]);
            split_bf2(*(const float2*)&cA[(rb + 8) * 24 + 2 * tig + 8], ahi[mi][3], alo[mi][3]);
        }
#pragma unroll
        for (int j = 0; j < 4; j++) {
            int nb = wn * 32 + j * 8 + gid;
            if (TB) {
                split_bf2(*(const float2*)&cB[nb * 24 + 2 * tig],     bhi[j][0], blo[j][0]);
                split_bf2(*(const float2*)&cB[nb * 24 + 2 * tig + 8], bhi[j][1], blo[j][1]);
            } else {
                float2 q0 = make_float2(cB[(2 * tig) * 72 + nb],     cB[(2 * tig + 1) * 72 + nb]);
                float2 q1 = make_float2(cB[(2 * tig + 8) * 72 + nb], cB[(2 * tig + 9) * 72 + nb]);
                split_bf2(q0, bhi[j][0], blo[j][0]);
                split_bf2(q1, bhi[j][1], blo[j][1]);
            }
        }
#pragma unroll
        for (int mi = 0; mi < 2; mi++)
#pragma unroll
            for (int j = 0; j < 4; j++) {
                mma_bf16(acc[mi][j], ahi[mi][0], ahi[mi][1], ahi[mi][2], ahi[mi][3],
                         blo[j][0], blo[j][1]);
                mma_bf16(acc[mi][j], alo[mi][0], alo[mi][1], alo[mi][2], alo[mi][3],
                         bhi[j][0], bhi[j][1]);
                mma_bf16(acc[mi][j], ahi[mi][0], ahi[mi][1], ahi[mi][2], ahi[mi][3],
                         bhi[j][0], bhi[j][1]);
            }
        __syncthreads();
    }

#pragma unroll
    for (int mi = 0; mi < 2; mi++) {
#pragma unroll
        for (int j = 0; j < 4; j++) {
            long col = n0 + wn * 32 + j * 8 + 2 * tig;
            float bx = 0.f, by = 0.f;
            if (HASB) { bx = bias[col]; by = bias[col + 1]; }
            long r0 = m0 + wm * 32 + mi * 16 + gid;
            float v0x = acc[mi][j][0] * alpha + bx, v0y = acc[mi][j][1] * alpha + by;
            float v1x = acc[mi][j][2] * alpha + bx, v1y = acc[mi][j][3] * alpha + by;
            if (OM == 0) {
                float* C = (float*)Cv + (long)z * cB;
                *(float2*)&C[r0 * (long)ldc + col] = make_float2(v0x, v0y);
                *(float2*)&C[(r0 + 8) * (long)ldc + col] = make_float2(v1x, v1y);
            } else {
                __half* C = (__half*)Cv + (long)z * cB;
                *(__half2*)&C[r0 * (long)ldc + col] = __floats2half2_rn(v0x, v0y);
                *(__half2*)&C[(r0 + 8) * (long)ldc + col] = __floats2half2_rn(v1x, v1y);
            }
        }
    }
}

// ---------------- kv post: rmsnorm latent + rope k_pe -> g_kfh (fp16) ----------------
__global__ __launch_bounds__(128)
void kv_post(const float* __restrict__ freqs, const float* __restrict__ knw)
{
    int bs = blockIdx.x;
    int s = bs & (S_ - 1);
    int tid = threadIdx.x;
    const float* row = g_kvt + (long)bs * CD;
    __half* out = g_kfh + (long)bs * CD;

    float ss = 0.f;
    for (int i = tid; i < RK; i += 128) { float v = row[i]; ss += v * v; }
    __shared__ float red[128];
    red[tid] = ss;
    __syncthreads();
    for (int o = 64; o > 0; o >>= 1) {
        if (tid < o) red[tid] += red[tid + o];
        __syncthreads();
    }
    __shared__ float rinv;
    if (tid == 0) rinv = rsqrtf(red[0] * (1.0f / RK) + EPS_);
    __syncthreads();
    float rv = rinv;
    for (int i = tid; i < RK; i += 128)
        out[i] = __float2half_rn(row[i] * rv * knw[i]);

    if (tid < ROPE_ / 2) {
        float a = row[RK + 2 * tid];
        float b = row[RK + 2 * tid + 1];
        float f = freqs[(long)s * 32 + tid];
        float sn, cs;
        sincosf(f, &sn, &cs);
        *(__half2*)&out[RK + 2 * tid] =
            __floats2half2_rn(a * cs - b * sn, a * sn + b * cs);
    }
}

// ---------------- V transpose: g_kfh[:, :512] -> g_kvT[b][d][s] (fp16) ----------------
__global__ __launch_bounds__(256)
void v_transpose()
{
    __shared__ __half t[32][33];
    int d0 = blockIdx.x * 32, s0 = blockIdx.y * 32, b = blockIdx.z;
    int tx = threadIdx.x & 31, ty = threadIdx.x >> 5;   // 8 rows per iter
#pragma unroll
    for (int i = 0; i < 32; i += 8)
        t[ty + i][tx] = g_kfh[((size_t)(b * S_ + s0 + ty + i)) * CD + d0 + tx];
    __syncthreads();
#pragma unroll
    for (int i = 0; i < 32; i += 8)
        g_kvT[((size_t)(b * RK + d0 + ty + i)) * S_ + s0 + tx] = t[tx][ty + i];
}

// ---------------- q rope (raw fp32 in, fp16 out, scaled) ----------------
__global__ __launch_bounds__(512)
void q_rope(const float* __restrict__ freqs)
{
    int bs = blockIdx.x;
    int s = bs & (S_ - 1);
    int tid = threadIdx.x;
    int h = tid >> 5, i = tid & 31;
    const float* qr = g_q + (long)bs * QBROW + h * QK_HD + NOPE_;
    float a = qr[2 * i], b = qr[2 * i + 1];
    float f = freqs[(long)s * 32 + i];
    float sn, cs;
    sincosf(f, &sn, &cs);
    __half* o = g_qfh + ((long)bs * H_ + h) * CD + RK;
    *(__half2*)&o[2 * i] =
        __floats2half2_rn((a * cs - b * sn) * SCALE_, (a * sn + b * cs) * SCALE_);
}

// ---------------- flash MQA: full fp16 (scores + PV) ----------------
// Block: 4 tokens x 16 heads = 64 q-rows. TK=32 keys/tile, cp.async.
// smem (words): sq fp16 64x292 | sk fp16 32x292 | svT fp16 512x20 |
//               sP fp32 64x36 (stats cols 32..34) | sPh fp16 64x20.
// Scores: warps 0..1, 32 rows x 32 keys each (fp16 k16, 36 chunks).
// PV: all 8 warps, 64 rows x 64 V-cols each (fp16 k16, 2 chunks).
#define OQ_ 0
#define OK_ 18688
#define OV_ 28032
#define OP_ 38272
#define OPH_ 40576
#define FLASH_SMEM ((OPH_ + 64 * 20) * 4)   // 167424 B

__global__ __launch_bounds__(256, 1)
void flash_tc()
{
    extern __shared__ uint32_t fsm[];
    uint32_t* sq  = fsm + OQ_;
    uint32_t* sk  = fsm + OK_;
    uint32_t* sv  = fsm + OV_;
    float*    sP  = (float*)(fsm + OP_);
    uint32_t* sPh = fsm + OPH_;

    int qs = blockIdx.x * 4;
    int b  = blockIdx.y;
    int tid = threadIdx.x;
    int w = tid >> 5, lane = tid & 31, gid = lane >> 2, tig = lane & 3;
    int bS = b * S_;

    uint32_t squ = sm_u32(sq), sku = sm_u32(sk), svu = sm_u32(sv);
    const uint32_t* qw = (const uint32_t*)g_qfh;
    const uint32_t* kw = (const uint32_t*)g_kfh;
    const uint32_t* vw = (const uint32_t*)g_kvT;

    // prologue: q tile (64 rows x 72 chunks of 16B)
    for (int c = tid; c < 64 * 72; c += 256) {
        int row = c / 72, ch = c - row * 72;
        int tok = row >> 4, h = row & 15;
        CPA16(squ + (row * 292 + ch * 4) * 4,
              &qw[((long)(bS + qs + tok) * H_ + h) * 288 + ch * 4]);
    }
    // K/V tile 0
    {
        int t0 = 0;
        for (int c = tid; c < 4352; c += 256) {
            if (c < 2304) {
                int r = c / 72, ch = c - r * 72;
                CPA16(sku + (r * 292 + ch * 4) * 4, &kw[(long)(bS + t0 + r) * 288 + ch * 4]);
            } else {
                int c2 = c - 2304;
                int d = c2 >> 2, ch = c2 & 3;
                CPA16(svu + (d * 20 + ch * 4) * 4,
                      &vw[((long)b * RK + d) * (S_ / 2) + (t0 >> 1) + ch * 4]);
            }
        }
    }
    CPCOMMIT();
    if (tid < 64) { sP[tid * 36 + 32] = -3.0e38f; sP[tid * 36 + 33] = 0.f; }

    float oacc[4][8][4];
#pragma unroll
    for (int rg = 0; rg < 4; rg++)
#pragma unroll
        for (int j = 0; j < 8; j++)
#pragma unroll
            for (int e = 0; e < 4; e++) oacc[rg][j][e] = 0.f;

    int ntk = qs / 32 + 1;

    for (int kt = 0; kt < ntk; kt++) {
        int t0 = kt * 32;
        CPWAIT(0);
        __syncthreads();

        // ---- scores: warps 0..1, 32 rows x 32 keys each ----
        if (w < 2) {
            int rb0 = w * 32;
            float sc[2][4][4];
#pragma unroll
            for (int mi = 0; mi < 2; mi++)
#pragma unroll
                for (int j = 0; j < 4; j++)
#pragma unroll
                    for (int e = 0; e < 4; e++) sc[mi][j][e] = 0.f;
#pragma unroll 4
            for (int kk = 0; kk < 36; kk++) {
                int kc = kk * 8;
                uint32_t a[2][4];
#pragma unroll
                for (int mi = 0; mi < 2; mi++) {
                    int r0 = rb0 + mi * 16 + gid;
                    a[mi][0] = sq[r0 * 292 + kc + tig];
                    a[mi][1] = sq[(r0 + 8) * 292 + kc + tig];
                    a[mi][2] = sq[r0 * 292 + kc + tig + 4];
                    a[mi][3] = sq[(r0 + 8) * 292 + kc + tig + 4];
                }
#pragma unroll
                for (int j = 0; j < 4; j++) {
                    int nb = j * 8 + gid;
                    uint32_t b0 = sk[nb * 292 + kc + tig];
                    uint32_t b1 = sk[nb * 292 + kc + tig + 4];
                    mma_f16(sc[0][j], a[0][0], a[0][1], a[0][2], a[0][3], b0, b1);
                    mma_f16(sc[1][j], a[1][0], a[1][1], a[1][2], a[1][3], b0, b1);
                }
            }
#pragma unroll
            for (int mi = 0; mi < 2; mi++)
#pragma unroll
                for (int j = 0; j < 4; j++) {
                    int r0 = rb0 + mi * 16 + gid;
                    int c0 = j * 8 + 2 * tig;
                    *(float2*)&sP[r0 * 36 + c0] = make_float2(sc[mi][j][0], sc[mi][j][1]);
                    *(float2*)&sP[(r0 + 8) * 36 + c0] = make_float2(sc[mi][j][2], sc[mi][j][3]);
                }
        }
        __syncthreads();

        // ---- online softmax (64 threads); causal mask; P -> fp16 ----
        if (tid < 64) {
            int row = tid;
            int spos = qs + (row >> 4);
            float* pr = sP + row * 36;
            float v[32];
            float mo = pr[32], mx = mo;
#pragma unroll
            for (int j = 0; j < 32; j++) {
                float x = pr[j];
                if (t0 + j > spos) x = -1.0e30f;
                v[j] = x;
                mx = fmaxf(mx, x);
            }
            float al = __expf(mo - mx);
            float sum = 0.f;
#pragma unroll
            for (int j = 0; j < 32; j++) {
                v[j] = __expf(v[j] - mx);
                sum += v[j];
            }
#pragma unroll
            for (int jw = 0; jw < 16; jw++) {
                __half2 h = __floats2half2_rn(v[2 * jw], v[2 * jw + 1]);
                sPh[row * 20 + jw] = *(uint32_t*)&h;
            }
            pr[32] = mx;
            pr[33] = pr[33] * al + sum;
            pr[34] = al;
        }
        __syncthreads();

        // ---- PV (fp16): all 8 warps, 64 rows x 64 V-cols each ----
        {
            float al0[4], al1[4];
#pragma unroll
            for (int rg = 0; rg < 4; rg++) {
                al0[rg] = sP[(rg * 16 + gid) * 36 + 34];
                al1[rg] = sP[(rg * 16 + gid + 8) * 36 + 34];
            }
#pragma unroll
            for (int rg = 0; rg < 4; rg++)
#pragma unroll
                for (int j = 0; j < 8; j++) {
                    oacc[rg][j][0] *= al0[rg]; oacc[rg][j][1] *= al0[rg];
                    oacc[rg][j][2] *= al1[rg]; oacc[rg][j][3] *= al1[rg];
                }
#pragma unroll
            for (int kk = 0; kk < 2; kk++) {
                int kc = kk * 8;
                uint32_t A0[4], A1[4], A2[4], A3[4];
#pragma unroll
                for (int rg = 0; rg < 4; rg++) {
                    A0[rg] = sPh[(rg * 16 + gid) * 20 + kc + tig];
                    A1[rg] = sPh[(rg * 16 + gid + 8) * 20 + kc + tig];
                    A2[rg] = sPh[(rg * 16 + gid) * 20 + kc + tig + 4];
                    A3[rg] = sPh[(rg * 16 + gid + 8) * 20 + kc + tig + 4];
                }
#pragma unroll
                for (int j = 0; j < 8; j++) {
                    int col = w * 64 + j * 8 + gid;
                    uint32_t b0 = sv[col * 20 + kc + tig];
                    uint32_t b1 = sv[col * 20 + kc + tig + 4];
#pragma unroll
                    for (int rg = 0; rg < 4; rg++)
                        mma_f16(oacc[rg][j], A0[rg], A1[rg], A2[rg], A3[rg], b0, b1);
                }
            }
        }
        __syncthreads();   // PV done -> safe to overwrite sk/sv

        if (kt + 1 < ntk) {
            int tn = t0 + 32;
            for (int c = tid; c < 4352; c += 256) {
                if (c < 2304) {
                    int r = c / 72, ch = c - r * 72;
                    CPA16(sku + (r * 292 + ch * 4) * 4, &kw[(long)(bS + tn + r) * 288 + ch * 4]);
                } else {
                    int c2 = c - 2304;
                    int d = c2 >> 2, ch = c2 & 3;
                    CPA16(svu + (d * 20 + ch * 4) * 4,
                          &vw[((long)b * RK + d) * (S_ / 2) + (tn >> 1) + ch * 4]);
                }
            }
        }
        CPCOMMIT();
    }

    // ---- epilogue: normalize + write raw fp32 g_ol ----
#pragma unroll
    for (int rg = 0; rg < 4; rg++) {
        float l0 = 1.f / sP[(rg * 16 + gid) * 36 + 33];
        float l1 = 1.f / sP[(rg * 16 + gid + 8) * 36 + 33];
        long base = ((long)(bS + qs + rg)) * OLROW;
        float* o0 = g_ol + base + (long)gid * RK + w * 64;
        float* o1 = g_ol + base + (long)(gid + 8) * RK + w * 64;
#pragma unroll
        for (int j = 0; j < 8; j++) {
            int col = j * 8 + 2 * tig;
            *(float2*)&o0[col] = make_float2(oacc[rg][j][0] * l0, oacc[rg][j][1] * l0);
            *(float2*)&o1[col] = make_float2(oacc[rg][j][2] * l1, oacc[rg][j][3] * l1);
        }
    }
}

// ---------------- launch ----------------
extern "C" void kernel_launch(void* const* d_in, const int* in_sizes, int n_in,
                              void* d_out, int out_size)
{
    const float* x      = (const float*)d_in[0];
    const float* freqs  = (const float*)d_in[1];
    // d_in[2] = mask (causal handled analytically)
    const float* wq_w   = (const float*)d_in[3];
    const float* wq_b   = (const float*)d_in[4];
    const float* wkva_w = (const float*)d_in[5];
    const float* wkva_b = (const float*)d_in[6];
    const float* knw    = (const float*)d_in[7];
    const float* wkvb   = (const float*)d_in[8];
    const float* wo_w   = (const float*)d_in[9];
    const float* wo_b   = (const float*)d_in[10];
    float* out = (float*)d_out;

    void *vq, *vqfh, *vkv, *vol, *vov;
    cudaGetSymbolAddress(&vq,   g_q);
    cudaGetSymbolAddress(&vqfh, g_qfh);
    cudaGetSymbolAddress(&vkv,  g_kvt);
    cudaGetSymbolAddress(&vol,  g_ol);
    cudaGetSymbolAddress(&vov,  g_ov);
    const float* pq  = (const float*)vq;
    const float* pol = (const float*)vol;
    const float* pov = (const float*)vov;

    cudaFuncSetAttribute(flash_tc, cudaFuncAttributeMaxDynamicSharedMemorySize, FLASH_SMEM);
    cudaFuncSetAttribute(gemm_bs<true, true, 0>,
                         cudaFuncAttributeMaxDynamicSharedMemorySize, GEMM_SMEM);
    cudaFuncSetAttribute(gemm_bs<false, false, 1>,
                         cudaFuncAttributeMaxDynamicSharedMemorySize, GEMM_SMEM);
    cudaFuncSetAttribute(gemm_bs<true, false, 0>,
                         cudaFuncAttributeMaxDynamicSharedMemorySize, GEMM_SMEM);

    // 1) kv = x @ wkv_a^T + b : (4096, 576) raw fp32
    gemm_bs<true, true, 0><<<dim3(CD / 64, BS / 128, 1), 256, GEMM_SMEM>>>(
        D_, x, D_, 0, wkva_w, D_, 0, vkv, CD, 0, wkva_b, 1.f);

    // 2) rmsnorm + rope K -> g_kfh (fp16), then transpose V -> g_kvT
    kv_post<<<BS, 128>>>(freqs, knw);
    v_transpose<<<dim3(RK / 32, S_ / 32, B_), 256>>>();

    // 3) q = x @ wq^T + b : (4096, 3072) raw fp32
    gemm_bs<true, true, 0><<<dim3(QBROW / 64, BS / 128, 1), 256, GEMM_SMEM>>>(
        D_, x, D_, 0, wq_w, D_, 0, vq, QBROW, 0, wq_b, 1.f);

    // 4) rope q_pe (scaled, fp16) -> g_qfh[..., 512:576]
    q_rope<<<BS, 512>>>(freqs);

    // 5) q_absorbed per head: q_nope @ wkv_b_nope (K,N), scaled, fp16 out -> g_qfh
    gemm_bs<false, false, 1><<<dim3(RK / 64, BS / 128, H_), 256, GEMM_SMEM>>>(
        NOPE_, pq, QBROW, QK_HD,
        wkvb, RK, (long)(NOPE_ + V_HD) * RK,
        vqfh, H_ * CD, CD, nullptr, SCALE_);

    // 6) causal flash MQA (fp16) -> g_ol (raw fp32)
    flash_tc<<<dim3(S_ / 4, B_), 256, FLASH_SMEM>>>();

    // 7) per-head V up-projection: o_lat @ wkv_b_v^T -> g_ov (raw fp32)
    gemm_bs<true, false, 0><<<dim3(V_HD / 64, BS / 128, H_), 256, GEMM_SMEM>>>(
        RK, pol, OLROW, RK,
        wkvb + (long)NOPE_ * RK, RK, (long)(NOPE_ + V_HD) * RK,
        vov, OVROW, V_HD, nullptr, 1.f);

    // 8) final: g_ov @ wo^T + wo_b -> out (fp32)
    gemm_bs<true, true, 0><<<dim3(D_ / 64, BS / 128, 1), 256, GEMM_SMEM>>>(
        OVROW, pov, OVROW, 0, wo_w, D_, 0, out, D_, 0, wo_b, 1.f);
}

// round 13
// speedup vs baseline: 1.4976x; 1.4976x over previous
#include <cuda_runtime.h>
#include <cuda_bf16.h>
#include <cuda_fp16.h>
#include <math.h>
#include <stdint.h>

// ---------------- problem constants ----------------
#define B_ 2
#define S_ 2048
#define D_ 2048
#define H_ 16
#define RK 512
#define ROPE_ 64
#define NOPE_ 128
#define QK_HD 192
#define V_HD 128
#define CD 576            // RK + ROPE
#define BS (B_ * S_)      // 4096
#define QROW (H_ * CD)    // 9216
#define QBROW (H_ * QK_HD)// 3072
#define OLROW (H_ * RK)   // 8192
#define OVROW (H_ * V_HD) // 2048
#define EPS_ 1.1920929e-07f
#define SCALE_ 0.0721687836487032f

// ---------------- scratch ----------------
__device__ float  g_q   [(size_t)BS * QBROW];      // raw fp32 q proj
__device__ float  g_kvt [(size_t)BS * CD];         // raw fp32 kv_a proj
__device__ __half g_qfh [(size_t)BS * H_ * CD];    // flash q (fp16)
__device__ __half g_kfh [(size_t)BS * CD];         // flash K (fp16, scores)
__device__ float  g_kfv [(size_t)BS * RK];         // flash V (tf32-rounded fp32, PV)
__device__ float  g_ol  [(size_t)BS * OLROW];      // raw fp32 flash out
__device__ float  g_ov  [(size_t)BS * OVROW];      // raw fp32 v-up out

// ---------------- helpers ----------------
__device__ __forceinline__ float tf32r(float x) {
    uint32_t u = __float_as_uint(x), o;
    asm("cvt.rna.tf32.f32 %0, %1;" : "=r"(o) : "r"(u));
    return __uint_as_float(o);
}
__device__ __forceinline__ void split_bf2(float2 p, uint32_t& hi, uint32_t& lo) {
    __nv_bfloat162 h = __float22bfloat162_rn(p);
    float hx = __low2float(h), hy = __high2float(h);
    __nv_bfloat162 l = __float22bfloat162_rn(make_float2(p.x - hx, p.y - hy));
    hi = *(uint32_t*)&h;
    lo = *(uint32_t*)&l;
}
__device__ __forceinline__ void mma_bf16(float c[4],
    uint32_t a0, uint32_t a1, uint32_t a2, uint32_t a3, uint32_t b0, uint32_t b1)
{
    asm volatile("mma.sync.aligned.m16n8k16.row.col.f32.bf16.bf16.f32 "
        "{%0,%1,%2,%3}, {%4,%5,%6,%7}, {%8,%9}, {%0,%1,%2,%3};\n"
        : "+f"(c[0]), "+f"(c[1]), "+f"(c[2]), "+f"(c[3])
        : "r"(a0), "r"(a1), "r"(a2), "r"(a3), "r"(b0), "r"(b1));
}
__device__ __forceinline__ void mma_f16(float c[4],
    uint32_t a0, uint32_t a1, uint32_t a2, uint32_t a3, uint32_t b0, uint32_t b1)
{
    asm volatile("mma.sync.aligned.m16n8k16.row.col.f32.f16.f16.f32 "
        "{%0,%1,%2,%3}, {%4,%5,%6,%7}, {%8,%9}, {%0,%1,%2,%3};\n"
        : "+f"(c[0]), "+f"(c[1]), "+f"(c[2]), "+f"(c[3])
        : "r"(a0), "r"(a1), "r"(a2), "r"(a3), "r"(b0), "r"(b1));
}
__device__ __forceinline__ void mma_tf32(float c[4],
    uint32_t a0, uint32_t a1, uint32_t a2, uint32_t a3, uint32_t b0, uint32_t b1)
{
    asm volatile("mma.sync.aligned.m16n8k8.row.col.f32.tf32.tf32.f32 "
        "{%0,%1,%2,%3}, {%4,%5,%6,%7}, {%8,%9}, {%0,%1,%2,%3};\n"
        : "+f"(c[0]), "+f"(c[1]), "+f"(c[2]), "+f"(c[3])
        : "r"(a0), "r"(a1), "r"(a2), "r"(a3), "r"(b0), "r"(b1));
}
__device__ __forceinline__ uint32_t sm_u32(const void* p) {
    return (uint32_t)__cvta_generic_to_shared(p);
}
#define CPA16(d, s) asm volatile("cp.async.ca.shared.global [%0], [%1], 16;\n" :: "r"(d), "l"(s))
#define CPCOMMIT()  asm volatile("cp.async.commit_group;\n")
#define CPWAIT(n)   asm volatile("cp.async.wait_group %0;\n" :: "n"(n))

// ---------------- bf16-split pipelined GEMM (R6, unchanged math) ----------------
// C = alpha * A*op(B) (+bias). A:(M,K) rm raw fp32. TB ? B:(N,K) rm : B:(K,N) rm.
// 128x64x16 tile, 3-stage cp.async. OM: 0 = fp32 out, 1 = fp16 out.
#define GA_ST 3072            // 128 * 24 floats per A stage
#define GB_ST 1536            // max(64*24, 16*72)
#define GEMM_SMEM ((3 * (GA_ST + GB_ST)) * 4)   // 55296 B dynamic
template<bool TB, bool HASB, int OM>
__global__ __launch_bounds__(256)
void gemm_bs(int K,
             const float* __restrict__ A, int lda, long aB,
             const float* __restrict__ Bm, int ldb, long bB,
             void* Cv, int ldc, long cB,
             const float* __restrict__ bias, float alpha)
{
    extern __shared__ float gsm[];
    float* sA = gsm;                  // 3 stages, pitch 24
    float* sB = gsm + 3 * GA_ST;

    int z = blockIdx.z;
    A  += (long)z * aB;
    Bm += (long)z * bB;

    long m0 = (long)blockIdx.y * 128;
    long n0 = (long)blockIdx.x * 64;
    int tid = threadIdx.x;
    int w = tid >> 5, lane = tid & 31, gid = lane >> 2, tig = lane & 3;
    int wm = w & 3, wn = w >> 2;

    uint32_t sAu = sm_u32(sA), sBu = sm_u32(sB);
    int nk = K / 16;

    auto issue = [&](int s, int kt) {
        int k0 = kt * 16;
#pragma unroll
        for (int i = 0; i < 2; i++) {
            int c = tid + i * 256;
            int r = c >> 2, kq = (c & 3) * 4;
            CPA16(sAu + (s * GA_ST + r * 24 + kq) * 4,
                  &A[(m0 + r) * (long)lda + k0 + kq]);
        }
        if (TB) {
            int r = tid >> 2, kq = (tid & 3) * 4;
            CPA16(sBu + (s * GB_ST + r * 24 + kq) * 4,
                  &Bm[(n0 + r) * (long)ldb + k0 + kq]);
        } else {
            int kk = tid >> 4, nq = (tid & 15) * 4;
            CPA16(sBu + (s * GB_ST + kk * 72 + nq) * 4,
                  &Bm[(long)(k0 + kk) * (long)ldb + n0 + nq]);
        }
    };

    float acc[2][4][4];
#pragma unroll
    for (int mi = 0; mi < 2; mi++)
#pragma unroll
        for (int j = 0; j < 4; j++)
#pragma unroll
            for (int e = 0; e < 4; e++) acc[mi][j][e] = 0.f;

    issue(0, 0); CPCOMMIT();
    if (nk > 1) { issue(1, 1); CPCOMMIT(); }

    for (int kt = 0; kt < nk; kt++) {
        CPWAIT(1);
        __syncthreads();
        if (kt + 2 < nk) { issue((kt + 2) % 3, kt + 2); CPCOMMIT(); }

        const float* cA = sA + (kt % 3) * GA_ST;
        const float* cB = sB + (kt % 3) * GB_ST;

        uint32_t ahi[2][4], alo[2][4], bhi[4][2], blo[4][2];
#pragma unroll
        for (int mi = 0; mi < 2; mi++) {
            int rb = wm * 32 + mi * 16 + gid;
            split_bf2(*(const float2*)&cA[rb * 24 + 2 * tig],           ahi[mi][0], alo[mi][0]);
            split_bf2(*(const float2*)&cA[(rb + 8) * 24 + 2 * tig],     ahi[mi][1], alo[mi][1]);
            split_bf2(*(const float2*)&cA[rb * 24 + 2 * tig + 8],       ahi[mi][2], alo[mi][2]);
            split_bf2(*(const float2*)&cA[(rb + 8) * 24 + 2 * tig + 8], ahi[mi][3], alo[mi][3]);
        }
#pragma unroll
        for (int j = 0; j < 4; j++) {
            int nb = wn * 32 + j * 8 + gid;
            if (TB) {
                split_bf2(*(const float2*)&cB[nb * 24 + 2 * tig],     bhi[j][0], blo[j][0]);
                split_bf2(*(const float2*)&cB[nb * 24 + 2 * tig + 8], bhi[j][1], blo[j][1]);
            } else {
                float2 q0 = make_float2(cB[(2 * tig) * 72 + nb],     cB[(2 * tig + 1) * 72 + nb]);
                float2 q1 = make_float2(cB[(2 * tig + 8) * 72 + nb], cB[(2 * tig + 9) * 72 + nb]);
                split_bf2(q0, bhi[j][0], blo[j][0]);
                split_bf2(q1, bhi[j][1], blo[j][1]);
            }
        }
#pragma unroll
        for (int mi = 0; mi < 2; mi++)
#pragma unroll
            for (int j = 0; j < 4; j++) {
                mma_bf16(acc[mi][j], ahi[mi][0], ahi[mi][1], ahi[mi][2], ahi[mi][3],
                         blo[j][0], blo[j][1]);
                mma_bf16(acc[mi][j], alo[mi][0], alo[mi][1], alo[mi][2], alo[mi][3],
                         bhi[j][0], bhi[j][1]);
                mma_bf16(acc[mi][j], ahi[mi][0], ahi[mi][1], ahi[mi][2], ahi[mi][3],
                         bhi[j][0], bhi[j][1]);
            }
        __syncthreads();
    }

#pragma unroll
    for (int mi = 0; mi < 2; mi++) {
#pragma unroll
        for (int j = 0; j < 4; j++) {
            long col = n0 + wn * 32 + j * 8 + 2 * tig;
            float bx = 0.f, by = 0.f;
            if (HASB) { bx = bias[col]; by = bias[col + 1]; }
            long r0 = m0 + wm * 32 + mi * 16 + gid;
            float v0x = acc[mi][j][0] * alpha + bx, v0y = acc[mi][j][1] * alpha + by;
            float v1x = acc[mi][j][2] * alpha + bx, v1y = acc[mi][j][3] * alpha + by;
            if (OM == 0) {
                float* C = (float*)Cv + (long)z * cB;
                *(float2*)&C[r0 * (long)ldc + col] = make_float2(v0x, v0y);
                *(float2*)&C[(r0 + 8) * (long)ldc + col] = make_float2(v1x, v1y);
            } else {
                __half* C = (__half*)Cv + (long)z * cB;
                *(__half2*)&C[r0 * (long)ldc + col] = __floats2half2_rn(v0x, v0y);
                *(__half2*)&C[(r0 + 8) * (long)ldc + col] = __floats2half2_rn(v1x, v1y);
            }
        }
    }
}

// ---------------- kv post: rmsnorm latent + rope -> g_kfh (fp16) + g_kfv (tf32) ----------------
__global__ __launch_bounds__(128)
void kv_post(const float* __restrict__ freqs, const float* __restrict__ knw)
{
    int bs = blockIdx.x;
    int s = bs & (S_ - 1);
    int tid = threadIdx.x;
    const float* row = g_kvt + (long)bs * CD;
    __half* oh = g_kfh + (long)bs * CD;
    float*  ov = g_kfv + (long)bs * RK;

    float ss = 0.f;
    for (int i = tid; i < RK; i += 128) { float v = row[i]; ss += v * v; }
    __shared__ float red[128];
    red[tid] = ss;
    __syncthreads();
    for (int o = 64; o > 0; o >>= 1) {
        if (tid < o) red[tid] += red[tid + o];
        __syncthreads();
    }
    __shared__ float rinv;
    if (tid == 0) rinv = rsqrtf(red[0] * (1.0f / RK) + EPS_);
    __syncthreads();
    float rv = rinv;
    for (int i = tid; i < RK; i += 128) {
        float x = row[i] * rv * knw[i];
        ov[i] = tf32r(x);
        oh[i] = __float2half_rn(x);
    }

    if (tid < ROPE_ / 2) {
        float a = row[RK + 2 * tid];
        float b = row[RK + 2 * tid + 1];
        float f = freqs[(long)s * 32 + tid];
        float sn, cs;
        sincosf(f, &sn, &cs);
        *(__half2*)&oh[RK + 2 * tid] =
            __floats2half2_rn(a * cs - b * sn, a * sn + b * cs);
    }
}

// ---------------- q rope (raw fp32 in, fp16 out, scaled) ----------------
__global__ __launch_bounds__(512)
void q_rope(const float* __restrict__ freqs)
{
    int bs = blockIdx.x;
    int s = bs & (S_ - 1);
    int tid = threadIdx.x;
    int h = tid >> 5, i = tid & 31;
    const float* qr = g_q + (long)bs * QBROW + h * QK_HD + NOPE_;
    float a = qr[2 * i], b = qr[2 * i + 1];
    float f = freqs[(long)s * 32 + i];
    float sn, cs;
    sincosf(f, &sn, &cs);
    __half* o = g_qfh + ((long)bs * H_ + h) * CD + RK;
    *(__half2*)&o[2 * i] =
        __floats2half2_rn((a * cs - b * sn) * SCALE_, (a * sn + b * cs) * SCALE_);
}

// ---------------- flash MQA: fp16 scores (4 warps) + tf32 PV (8 warps) ----------------
// Block: 4 tokens x 16 heads = 64 q-rows. TK=32 keys/tile, cp.async.
// smem (words): sq fp16 64x300 | sk fp16 32x300 | sv fp32 32x516 |
//               sP fp32 64x36 (stats cols 32..34).
#define SQW (64 * 300)
#define SKW (32 * 300)
#define SVW (32 * 516)
#define SPW (64 * 36)
#define FLASH_SMEM ((SQW + SKW + SVW + SPW) * 4)   // 190464 B

__global__ __launch_bounds__(256, 1)
void flash_tc()
{
    extern __shared__ uint32_t fsm[];
    uint32_t* sq  = fsm;
    uint32_t* skh = fsm + SQW;
    float*    sv  = (float*)(fsm + SQW + SKW);
    float*    sP  = (float*)(fsm + SQW + SKW + SVW);

    int qs = blockIdx.x * 4;
    int b  = blockIdx.y;
    int tid = threadIdx.x;
    int w = tid >> 5, lane = tid & 31, gid = lane >> 2, tig = lane & 3;
    int bS = b * S_;

    uint32_t squ = sm_u32(sq), sku = sm_u32(skh), svu = sm_u32(sv);
    const uint32_t* qw = (const uint32_t*)g_qfh;
    const uint32_t* kw = (const uint32_t*)g_kfh;
    const uint32_t* vw = (const uint32_t*)g_kfv;

    // prologue: q tile (64 rows x 72 chunks of 16B)
    for (int c = tid; c < 64 * 72; c += 256) {
        int row = c / 72, ch = c - row * 72;
        int tok = row >> 4, h = row & 15;
        CPA16(squ + (row * 300 + 4 * ch) * 4,
              &qw[((long)(bS + qs + tok) * H_ + h) * 288 + 4 * ch]);
    }
    // K/V tile 0
    for (int c = tid; c < 6400; c += 256) {
        if (c < 2304) {
            int r = c / 72, ch = c - r * 72;
            CPA16(sku + (r * 300 + 4 * ch) * 4, &kw[(long)(bS + r) * 288 + 4 * ch]);
        } else {
            int c2 = c - 2304;
            int r = c2 >> 7, ch = c2 & 127;
            CPA16(svu + (r * 516 + 4 * ch) * 4, &vw[(long)(bS + r) * 512 + 4 * ch]);
        }
    }
    CPCOMMIT();
    if (tid < 64) { sP[tid * 36 + 32] = -3.0e38f; sP[tid * 36 + 33] = 0.f; }

    float oacc[4][8][4];
#pragma unroll
    for (int rg = 0; rg < 4; rg++)
#pragma unroll
        for (int j = 0; j < 8; j++)
#pragma unroll
            for (int e = 0; e < 4; e++) oacc[rg][j][e] = 0.f;

    int ntk = qs / 32 + 1;

    for (int kt = 0; kt < ntk; kt++) {
        int t0 = kt * 32;
        CPWAIT(0);
        __syncthreads();

        // ---- scores: warps 0..3, 16 rows x 32 keys each, fp16 k16 x 36 chunks ----
        if (w < 4) {
            int rb = w * 16;
            const uint32_t* r0p = sq + (rb + gid) * 300;
            const uint32_t* r1p = sq + (rb + gid + 8) * 300;
            float sc[4][4];
#pragma unroll
            for (int j = 0; j < 4; j++)
#pragma unroll
                for (int e = 0; e < 4; e++) sc[j][e] = 0.f;
#pragma unroll 4
            for (int kk = 0; kk < 36; kk++) {
                int kc = kk * 8;
                uint32_t a0 = r0p[kc + tig];
                uint32_t a1 = r1p[kc + tig];
                uint32_t a2 = r0p[kc + tig + 4];
                uint32_t a3 = r1p[kc + tig + 4];
#pragma unroll
                for (int j = 0; j < 4; j++) {
                    int nb = j * 8 + gid;
                    uint32_t b0 = skh[nb * 300 + kc + tig];
                    uint32_t b1 = skh[nb * 300 + kc + tig + 4];
                    mma_f16(sc[j], a0, a1, a2, a3, b0, b1);
                }
            }
#pragma unroll
            for (int j = 0; j < 4; j++) {
                int c0 = j * 8 + 2 * tig;
                *(float2*)&sP[(rb + gid) * 36 + c0] = make_float2(sc[j][0], sc[j][1]);
                *(float2*)&sP[(rb + gid + 8) * 36 + c0] = make_float2(sc[j][2], sc[j][3]);
            }
        }
        __syncthreads();

        // ---- online softmax (64 threads); causal mask; P -> tf32 ----
        if (tid < 64) {
            int row = tid;
            int spos = qs + (row >> 4);
            float* pr = sP + row * 36;
            float v[32];
            float mo = pr[32], mx = mo;
#pragma unroll
            for (int j = 0; j < 32; j++) {
                float x = pr[j];
                if (t0 + j > spos) x = -1.0e30f;
                v[j] = x;
                mx = fmaxf(mx, x);
            }
            float al = __expf(mo - mx);
            float sum = 0.f;
#pragma unroll
            for (int j = 0; j < 32; j++) {
                float p = __expf(v[j] - mx);
                sum += p;
                pr[j] = tf32r(p);
            }
            pr[32] = mx;
            pr[33] = pr[33] * al + sum;
            pr[34] = al;
        }
        __syncthreads();

        // ---- PV (tf32): all 8 warps, 64 rows x 64 V-cols each ----
        {
            float al0[4], al1[4];
#pragma unroll
            for (int rg = 0; rg < 4; rg++) {
                al0[rg] = sP[(rg * 16 + gid) * 36 + 34];
                al1[rg] = sP[(rg * 16 + gid + 8) * 36 + 34];
            }
#pragma unroll
            for (int rg = 0; rg < 4; rg++)
#pragma unroll
                for (int j = 0; j < 8; j++) {
                    oacc[rg][j][0] *= al0[rg]; oacc[rg][j][1] *= al0[rg];
                    oacc[rg][j][2] *= al1[rg]; oacc[rg][j][3] *= al1[rg];
                }
#pragma unroll
            for (int kk = 0; kk < 4; kk++) {
                int kc = kk * 8;
                uint32_t A0[4], A1[4], A2[4], A3[4];
#pragma unroll
                for (int rg = 0; rg < 4; rg++) {
                    A0[rg] = __float_as_uint(sP[(rg * 16 + gid) * 36 + kc + tig]);
                    A1[rg] = __float_as_uint(sP[(rg * 16 + gid + 8) * 36 + kc + tig]);
                    A2[rg] = __float_as_uint(sP[(rg * 16 + gid) * 36 + kc + tig + 4]);
                    A3[rg] = __float_as_uint(sP[(rg * 16 + gid + 8) * 36 + kc + tig + 4]);
                }
#pragma unroll
                for (int j = 0; j < 8; j++) {
                    int col = w * 64 + j * 8 + gid;
                    uint32_t b0 = __float_as_uint(sv[(kc + tig) * 516 + col]);
                    uint32_t b1 = __float_as_uint(sv[(kc + tig + 4) * 516 + col]);
#pragma unroll
                    for (int rg = 0; rg < 4; rg++)
                        mma_tf32(oacc[rg][j], A0[rg], A1[rg], A2[rg], A3[rg], b0, b1);
                }
            }
        }
        __syncthreads();   // PV done -> safe to overwrite sk/sv

        if (kt + 1 < ntk) {
            int tn = t0 + 32;
            for (int c = tid; c < 6400; c += 256) {
                if (c < 2304) {
                    int r = c / 72, ch = c - r * 72;
                    CPA16(sku + (r * 300 + 4 * ch) * 4, &kw[(long)(bS + tn + r) * 288 + 4 * ch]);
                } else {
                    int c2 = c - 2304;
                    int r = c2 >> 7, ch = c2 & 127;
                    CPA16(svu + (r * 516 + 4 * ch) * 4, &vw[(long)(bS + tn + r) * 512 + 4 * ch]);
                }
            }
        }
        CPCOMMIT();
    }

    // ---- epilogue: normalize + write raw fp32 g_ol ----
#pragma unroll
    for (int rg = 0; rg < 4; rg++) {
        float l0 = 1.f / sP[(rg * 16 + gid) * 36 + 33];
        float l1 = 1.f / sP[(rg * 16 + gid + 8) * 36 + 33];
        long base = ((long)(bS + qs + rg)) * OLROW;
        float* o0 = g_ol + base + (long)gid * RK + w * 64;
        float* o1 = g_ol + base + (long)(gid + 8) * RK + w * 64;
#pragma unroll
        for (int j = 0; j < 8; j++) {
            int col = j * 8 + 2 * tig;
            *(float2*)&o0[col] = make_float2(oacc[rg][j][0] * l0, oacc[rg][j][1] * l0);
            *(float2*)&o1[col] = make_float2(oacc[rg][j][2] * l1, oacc[rg][j][3] * l1);
        }
    }
}

// ---------------- launch ----------------
extern "C" void kernel_launch(void* const* d_in, const int* in_sizes, int n_in,
                              void* d_out, int out_size)
{
    const float* x      = (const float*)d_in[0];
    const float* freqs  = (const float*)d_in[1];
    // d_in[2] = mask (causal handled analytically)
    const float* wq_w   = (const float*)d_in[3];
    const float* wq_b   = (const float*)d_in[4];
    const float* wkva_w = (const float*)d_in[5];
    const float* wkva_b = (const float*)d_in[6];
    const float* knw    = (const float*)d_in[7];
    const float* wkvb   = (const float*)d_in[8];
    const float* wo_w   = (const float*)d_in[9];
    const float* wo_b   = (const float*)d_in[10];
    float* out = (float*)d_out;

    void *vq, *vqfh, *vkv, *vol, *vov;
    cudaGetSymbolAddress(&vq,   g_q);
    cudaGetSymbolAddress(&vqfh, g_qfh);
    cudaGetSymbolAddress(&vkv,  g_kvt);
    cudaGetSymbolAddress(&vol,  g_ol);
    cudaGetSymbolAddress(&vov,  g_ov);
    const float* pq  = (const float*)vq;
    const float* pol = (const float*)vol;
    const float* pov = (const float*)vov;

    cudaFuncSetAttribute(flash_tc, cudaFuncAttributeMaxDynamicSharedMemorySize, FLASH_SMEM);
    cudaFuncSetAttribute(gemm_bs<true, true, 0>,
                         cudaFuncAttributeMaxDynamicSharedMemorySize, GEMM_SMEM);
    cudaFuncSetAttribute(gemm_bs<false, false, 1>,
                         cudaFuncAttributeMaxDynamicSharedMemorySize, GEMM_SMEM);
    cudaFuncSetAttribute(gemm_bs<true, false, 0>,
                         cudaFuncAttributeMaxDynamicSharedMemorySize, GEMM_SMEM);

    // 1) kv = x @ wkv_a^T + b : (4096, 576) raw fp32
    gemm_bs<true, true, 0><<<dim3(CD / 64, BS / 128, 1), 256, GEMM_SMEM>>>(
        D_, x, D_, 0, wkva_w, D_, 0, vkv, CD, 0, wkva_b, 1.f);

    // 2) rmsnorm + rope K -> g_kfh (fp16) + g_kfv (tf32 fp32)
    kv_post<<<BS, 128>>>(freqs, knw);

    // 3) q = x @ wq^T + b : (4096, 3072) raw fp32
    gemm_bs<true, true, 0><<<dim3(QBROW / 64, BS / 128, 1), 256, GEMM_SMEM>>>(
        D_, x, D_, 0, wq_w, D_, 0, vq, QBROW, 0, wq_b, 1.f);

    // 4) rope q_pe (scaled, fp16) -> g_qfh[..., 512:576]
    q_rope<<<BS, 512>>>(freqs);

    // 5) q_absorbed per head: q_nope @ wkv_b_nope (K,N), scaled, fp16 out -> g_qfh
    gemm_bs<false, false, 1><<<dim3(RK / 64, BS / 128, H_), 256, GEMM_SMEM>>>(
        NOPE_, pq, QBROW, QK_HD,
        wkvb, RK, (long)(NOPE_ + V_HD) * RK,
        vqfh, H_ * CD, CD, nullptr, SCALE_);

    // 6) causal flash MQA -> g_ol (raw fp32)
    flash_tc<<<dim3(S_ / 4, B_), 256, FLASH_SMEM>>>();

    // 7) per-head V up-projection: o_lat @ wkv_b_v^T -> g_ov (raw fp32)
    gemm_bs<true, false, 0><<<dim3(V_HD / 64, BS / 128, H_), 256, GEMM_SMEM>>>(
        RK, pol, OLROW, RK,
        wkvb + (long)NOPE_ * RK, RK, (long)(NOPE_ + V_HD) * RK,
        vov, OVROW, V_HD, nullptr, 1.f);

    // 8) final: g_ov @ wo^T + wo_b -> out (fp32)
    gemm_bs<true, true, 0><<<dim3(D_ / 64, BS / 128, 1), 256, GEMM_SMEM>>>(
        OVROW, pov, OVROW, 0, wo_w, D_, 0, out, D_, 0, wo_b, 1.f);
}

// round 14
// speedup vs baseline: 1.6129x; 1.0770x over previous
#include <cuda_runtime.h>
#include <cuda_bf16.h>
#include <cuda_fp16.h>
#include <math.h>
#include <stdint.h>

// ---------------- problem constants ----------------
#define B_ 2
#define S_ 2048
#define D_ 2048
#define H_ 16
#define RK 512
#define ROPE_ 64
#define NOPE_ 128
#define QK_HD 192
#define V_HD 128
#define CD 576            // RK + ROPE
#define BS (B_ * S_)      // 4096
#define QROW (H_ * CD)    // 9216
#define QBROW (H_ * QK_HD)// 3072
#define OLROW (H_ * RK)   // 8192
#define OVROW (H_ * V_HD) // 2048
#define EPS_ 1.1920929e-07f
#define SCALE_ 0.0721687836487032f

// ---------------- scratch ----------------
__device__ float  g_q   [(size_t)BS * QBROW];      // raw fp32 q proj
__device__ float  g_kvt [(size_t)BS * CD];         // raw fp32 kv_a proj
__device__ __half g_qfh [(size_t)BS * H_ * CD];    // flash q (fp16)
__device__ __half g_kfh [(size_t)BS * CD];         // flash K (fp16, scores; cols 0..511 = V)
__device__ __half g_kvT [(size_t)B_ * RK * S_];    // flash V transposed [b][d][s] fp16
__device__ float  g_ol  [(size_t)BS * OLROW];      // raw fp32 flash out
__device__ float  g_ov  [(size_t)BS * OVROW];      // raw fp32 v-up out

// ---------------- helpers ----------------
__device__ __forceinline__ void split_bf2(float2 p, uint32_t& hi, uint32_t& lo) {
    __nv_bfloat162 h = __float22bfloat162_rn(p);
    float hx = __low2float(h), hy = __high2float(h);
    __nv_bfloat162 l = __float22bfloat162_rn(make_float2(p.x - hx, p.y - hy));
    hi = *(uint32_t*)&h;
    lo = *(uint32_t*)&l;
}
__device__ __forceinline__ void mma_bf16(float c[4],
    uint32_t a0, uint32_t a1, uint32_t a2, uint32_t a3, uint32_t b0, uint32_t b1)
{
    asm volatile("mma.sync.aligned.m16n8k16.row.col.f32.bf16.bf16.f32 "
        "{%0,%1,%2,%3}, {%4,%5,%6,%7}, {%8,%9}, {%0,%1,%2,%3};\n"
        : "+f"(c[0]), "+f"(c[1]), "+f"(c[2]), "+f"(c[3])
        : "r"(a0), "r"(a1), "r"(a2), "r"(a3), "r"(b0), "r"(b1));
}
__device__ __forceinline__ void mma_f16(float c[4],
    uint32_t a0, uint32_t a1, uint32_t a2, uint32_t a3, uint32_t b0, uint32_t b1)
{
    asm volatile("mma.sync.aligned.m16n8k16.row.col.f32.f16.f16.f32 "
        "{%0,%1,%2,%3}, {%4,%5,%6,%7}, {%8,%9}, {%0,%1,%2,%3};\n"
        : "+f"(c[0]), "+f"(c[1]), "+f"(c[2]), "+f"(c[3])
        : "r"(a0), "r"(a1), "r"(a2), "r"(a3), "r"(b0), "r"(b1));
}
__device__ __forceinline__ uint32_t sm_u32(const void* p) {
    return (uint32_t)__cvta_generic_to_shared(p);
}
#define CPA16(d, s) asm volatile("cp.async.ca.shared.global [%0], [%1], 16;\n" :: "r"(d), "l"(s))
#define CPCOMMIT()  asm volatile("cp.async.commit_group;\n")
#define CPWAIT(n)   asm volatile("cp.async.wait_group %0;\n" :: "n"(n))

// ---------------- bf16-split pipelined GEMM (R6, unchanged math) ----------------
// C = alpha * A*op(B) (+bias). A:(M,K) rm raw fp32. TB ? B:(N,K) rm : B:(K,N) rm.
// 128x64x16 tile, 3-stage cp.async. OM: 0 = fp32 out, 1 = fp16 out.
#define GA_ST 3072            // 128 * 24 floats per A stage
#define GB_ST 1536            // max(64*24, 16*72)
#define GEMM_SMEM ((3 * (GA_ST + GB_ST)) * 4)   // 55296 B dynamic
template<bool TB, bool HASB, int OM>
__global__ __launch_bounds__(256)
void gemm_bs(int K,
             const float* __restrict__ A, int lda, long aB,
             const float* __restrict__ Bm, int ldb, long bB,
             void* Cv, int ldc, long cB,
             const float* __restrict__ bias, float alpha)
{
    extern __shared__ float gsm[];
    float* sA = gsm;                  // 3 stages, pitch 24
    float* sB = gsm + 3 * GA_ST;

    int z = blockIdx.z;
    A  += (long)z * aB;
    Bm += (long)z * bB;

    long m0 = (long)blockIdx.y * 128;
    long n0 = (long)blockIdx.x * 64;
    int tid = threadIdx.x;
    int w = tid >> 5, lane = tid & 31, gid = lane >> 2, tig = lane & 3;
    int wm = w & 3, wn = w >> 2;

    uint32_t sAu = sm_u32(sA), sBu = sm_u32(sB);
    int nk = K / 16;

    auto issue = [&](int s, int kt) {
        int k0 = kt * 16;
#pragma unroll
        for (int i = 0; i < 2; i++) {
            int c = tid + i * 256;
            int r = c >> 2, kq = (c & 3) * 4;
            CPA16(sAu + (s * GA_ST + r * 24 + kq) * 4,
                  &A[(m0 + r) * (long)lda + k0 + kq]);
        }
        if (TB) {
            int r = tid >> 2, kq = (tid & 3) * 4;
            CPA16(sBu + (s * GB_ST + r * 24 + kq) * 4,
                  &Bm[(n0 + r) * (long)ldb + k0 + kq]);
        } else {
            int kk = tid >> 4, nq = (tid & 15) * 4;
            CPA16(sBu + (s * GB_ST + kk * 72 + nq) * 4,
                  &Bm[(long)(k0 + kk) * (long)ldb + n0 + nq]);
        }
    };

    float acc[2][4][4];
#pragma unroll
    for (int mi = 0; mi < 2; mi++)
#pragma unroll
        for (int j = 0; j < 4; j++)
#pragma unroll
            for (int e = 0; e < 4; e++) acc[mi][j][e] = 0.f;

    issue(0, 0); CPCOMMIT();
    if (nk > 1) { issue(1, 1); CPCOMMIT(); }

    for (int kt = 0; kt < nk; kt++) {
        CPWAIT(1);
        __syncthreads();
        if (kt + 2 < nk) { issue((kt + 2) % 3, kt + 2); CPCOMMIT(); }

        const float* cA = sA + (kt % 3) * GA_ST;
        const float* cB = sB + (kt % 3) * GB_ST;

        uint32_t ahi[2][4], alo[2][4], bhi[4][2], blo[4][2];
#pragma unroll
        for (int mi = 0; mi < 2; mi++) {
            int rb = wm * 32 + mi * 16 + gid;
            split_bf2(*(const float2*)&cA[rb * 24 + 2 * tig],           ahi[mi][0], alo[mi][0]);
            split_bf2(*(const float2*)&cA[(rb + 8) * 24 + 2 * tig],     ahi[mi][1], alo[mi][1]);
            split_bf2(*(const float2*)&cA[rb * 24 + 2 * tig + 8],       ahi[mi][2], alo[mi][2]);
            split_bf2(*(const float2*)&cA[(rb + 8) * 24 + 2 * tig + 8], ahi[mi][3], alo[mi][3]);
        }
#pragma unroll
        for (int j = 0; j < 4; j++) {
            int nb = wn * 32 + j * 8 + gid;
            if (TB) {
                split_bf2(*(const float2*)&cB[nb * 24 + 2 * tig],     bhi[j][0], blo[j][0]);
                split_bf2(*(const float2*)&cB[nb * 24 + 2 * tig + 8], bhi[j][1], blo[j][1]);
            } else {
                float2 q0 = make_float2(cB[(2 * tig) * 72 + nb],     cB[(2 * tig + 1) * 72 + nb]);
                float2 q1 = make_float2(cB[(2 * tig + 8) * 72 + nb], cB[(2 * tig + 9) * 72 + nb]);
                split_bf2(q0, bhi[j][0], blo[j][0]);
                split_bf2(q1, bhi[j][1], blo[j][1]);
            }
        }
#pragma unroll
        for (int mi = 0; mi < 2; mi++)
#pragma unroll
            for (int j = 0; j < 4; j++) {
                mma_bf16(acc[mi][j], ahi[mi][0], ahi[mi][1], ahi[mi][2], ahi[mi][3],
                         blo[j][0], blo[j][1]);
                mma_bf16(acc[mi][j], alo[mi][0], alo[mi][1], alo[mi][2], alo[mi][3],
                         bhi[j][0], bhi[j][1]);
                mma_bf16(acc[mi][j], ahi[mi][0], ahi[mi][1], ahi[mi][2], ahi[mi][3],
                         bhi[j][0], bhi[j][1]);
            }
        __syncthreads();
    }

#pragma unroll
    for (int mi = 0; mi < 2; mi++) {
#pragma unroll
        for (int j = 0; j < 4; j++) {
            long col = n0 + wn * 32 + j * 8 + 2 * tig;
            float bx = 0.f, by = 0.f;
            if (HASB) { bx = bias[col]; by = bias[col + 1]; }
            long r0 = m0 + wm * 32 + mi * 16 + gid;
            float v0x = acc[mi][j][0] * alpha + bx, v0y = acc[mi][j][1] * alpha + by;
            float v1x = acc[mi][j][2] * alpha + bx, v1y = acc[mi][j][3] * alpha + by;
            if (OM == 0) {
                float* C = (float*)Cv + (long)z * cB;
                *(float2*)&C[r0 * (long)ldc + col] = make_float2(v0x, v0y);
                *(float2*)&C[(r0 + 8) * (long)ldc + col] = make_float2(v1x, v1y);
            } else {
                __half* C = (__half*)Cv + (long)z * cB;
                *(__half2*)&C[r0 * (long)ldc + col] = __floats2half2_rn(v0x, v0y);
                *(__half2*)&C[(r0 + 8) * (long)ldc + col] = __floats2half2_rn(v1x, v1y);
            }
        }
    }
}

// ---------------- kv post: rmsnorm latent + rope k_pe -> g_kfh (fp16) ----------------
__global__ __launch_bounds__(128)
void kv_post(const float* __restrict__ freqs, const float* __restrict__ knw)
{
    int bs = blockIdx.x;
    int s = bs & (S_ - 1);
    int tid = threadIdx.x;
    const float* row = g_kvt + (long)bs * CD;
    __half* oh = g_kfh + (long)bs * CD;

    float ss = 0.f;
    for (int i = tid; i < RK; i += 128) { float v = row[i]; ss += v * v; }
    __shared__ float red[128];
    red[tid] = ss;
    __syncthreads();
    for (int o = 64; o > 0; o >>= 1) {
        if (tid < o) red[tid] += red[tid + o];
        __syncthreads();
    }
    __shared__ float rinv;
    if (tid == 0) rinv = rsqrtf(red[0] * (1.0f / RK) + EPS_);
    __syncthreads();
    float rv = rinv;
    for (int i = tid; i < RK; i += 128)
        oh[i] = __float2half_rn(row[i] * rv * knw[i]);

    if (tid < ROPE_ / 2) {
        float a = row[RK + 2 * tid];
        float b = row[RK + 2 * tid + 1];
        float f = freqs[(long)s * 32 + tid];
        float sn, cs;
        sincosf(f, &sn, &cs);
        *(__half2*)&oh[RK + 2 * tid] =
            __floats2half2_rn(a * cs - b * sn, a * sn + b * cs);
    }
}

// ---------------- V transpose: g_kfh[:, :512] -> g_kvT[b][d][s] (fp16) ----------------
__global__ __launch_bounds__(256)
void v_transpose()
{
    __shared__ __half t[32][33];
    int d0 = blockIdx.x * 32, s0 = blockIdx.y * 32, b = blockIdx.z;
    int tx = threadIdx.x & 31, ty = threadIdx.x >> 5;   // 8 rows per iter
#pragma unroll
    for (int i = 0; i < 32; i += 8)
        t[ty + i][tx] = g_kfh[((size_t)(b * S_ + s0 + ty + i)) * CD + d0 + tx];
    __syncthreads();
#pragma unroll
    for (int i = 0; i < 32; i += 8)
        g_kvT[((size_t)(b * RK + d0 + ty + i)) * S_ + s0 + tx] = t[tx][ty + i];
}

// ---------------- q rope (raw fp32 in, fp16 out, scaled) ----------------
__global__ __launch_bounds__(512)
void q_rope(const float* __restrict__ freqs)
{
    int bs = blockIdx.x;
    int s = bs & (S_ - 1);
    int tid = threadIdx.x;
    int h = tid >> 5, i = tid & 31;
    const float* qr = g_q + (long)bs * QBROW + h * QK_HD + NOPE_;
    float a = qr[2 * i], b = qr[2 * i + 1];
    float f = freqs[(long)s * 32 + i];
    float sn, cs;
    sincosf(f, &sn, &cs);
    __half* o = g_qfh + ((long)bs * H_ + h) * CD + RK;
    *(__half2*)&o[2 * i] =
        __floats2half2_rn((a * cs - b * sn) * SCALE_, (a * sn + b * cs) * SCALE_);
}

// ---------------- flash MQA: fp16 scores (4 warps) + fp16 PV (8 warps) ----------------
// Block: 4 tokens x 16 heads = 64 q-rows. TK=32 keys/tile, cp.async.
// smem (words): sq fp16 64x300 | sk fp16 32x300 | sv fp16 512x36 ([d][s-word], pitch 36
//   => B-load banks gid*4+tig, conflict-free) | sP fp32 64x36 (stats 32..34) | sPh fp16 64x20.
#define SQW (64 * 300)
#define SKW (32 * 300)
#define SVW (512 * 36)
#define SPW (64 * 36)
#define SPHW (64 * 20)
#define FLASH_SMEM ((SQW + SKW + SVW + SPW + SPHW) * 4)   // 203264 B

__global__ __launch_bounds__(256, 1)
void flash_tc()
{
    extern __shared__ uint32_t fsm[];
    uint32_t* sq  = fsm;
    uint32_t* skh = fsm + SQW;
    uint32_t* sv  = fsm + SQW + SKW;
    float*    sP  = (float*)(fsm + SQW + SKW + SVW);
    uint32_t* sPh = fsm + SQW + SKW + SVW + SPW;

    int qs = blockIdx.x * 4;
    int b  = blockIdx.y;
    int tid = threadIdx.x;
    int w = tid >> 5, lane = tid & 31, gid = lane >> 2, tig = lane & 3;
    int bS = b * S_;

    uint32_t squ = sm_u32(sq), sku = sm_u32(skh), svu = sm_u32(sv);
    const uint32_t* qw = (const uint32_t*)g_qfh;
    const uint32_t* kw = (const uint32_t*)g_kfh;
    const uint32_t* vw = (const uint32_t*)g_kvT;   // [b][d] rows of S_/2 words

    // prologue: q tile (64 rows x 72 chunks of 16B)
    for (int c = tid; c < 64 * 72; c += 256) {
        int row = c / 72, ch = c - row * 72;
        int tok = row >> 4, h = row & 15;
        CPA16(squ + (row * 300 + 4 * ch) * 4,
              &qw[((long)(bS + qs + tok) * H_ + h) * 288 + 4 * ch]);
    }
    // K/V tile 0: K 2304 chunks + V 2048 chunks (512 d-rows x 4)
    for (int c = tid; c < 4352; c += 256) {
        if (c < 2304) {
            int r = c / 72, ch = c - r * 72;
            CPA16(sku + (r * 300 + 4 * ch) * 4, &kw[(long)(bS + r) * 288 + 4 * ch]);
        } else {
            int c2 = c - 2304;
            int d = c2 >> 2, ch = c2 & 3;
            CPA16(svu + (d * 36 + 4 * ch) * 4,
                  &vw[((long)b * RK + d) * (S_ / 2) + 4 * ch]);
        }
    }
    CPCOMMIT();
    if (tid < 64) { sP[tid * 36 + 32] = -3.0e38f; sP[tid * 36 + 33] = 0.f; }

    float oacc[4][8][4];
#pragma unroll
    for (int rg = 0; rg < 4; rg++)
#pragma unroll
        for (int j = 0; j < 8; j++)
#pragma unroll
            for (int e = 0; e < 4; e++) oacc[rg][j][e] = 0.f;

    int ntk = qs / 32 + 1;

    for (int kt = 0; kt < ntk; kt++) {
        int t0 = kt * 32;
        CPWAIT(0);
        __syncthreads();

        // ---- scores: warps 0..3, 16 rows x 32 keys each, fp16 k16 x 36 chunks ----
        if (w < 4) {
            int rb = w * 16;
            const uint32_t* r0p = sq + (rb + gid) * 300;
            const uint32_t* r1p = sq + (rb + gid + 8) * 300;
            float sc[4][4];
#pragma unroll
            for (int j = 0; j < 4; j++)
#pragma unroll
                for (int e = 0; e < 4; e++) sc[j][e] = 0.f;
#pragma unroll 4
            for (int kk = 0; kk < 36; kk++) {
                int kc = kk * 8;
                uint32_t a0 = r0p[kc + tig];
                uint32_t a1 = r1p[kc + tig];
                uint32_t a2 = r0p[kc + tig + 4];
                uint32_t a3 = r1p[kc + tig + 4];
#pragma unroll
                for (int j = 0; j < 4; j++) {
                    int nb = j * 8 + gid;
                    uint32_t b0 = skh[nb * 300 + kc + tig];
                    uint32_t b1 = skh[nb * 300 + kc + tig + 4];
                    mma_f16(sc[j], a0, a1, a2, a3, b0, b1);
                }
            }
#pragma unroll
            for (int j = 0; j < 4; j++) {
                int c0 = j * 8 + 2 * tig;
                *(float2*)&sP[(rb + gid) * 36 + c0] = make_float2(sc[j][0], sc[j][1]);
                *(float2*)&sP[(rb + gid + 8) * 36 + c0] = make_float2(sc[j][2], sc[j][3]);
            }
        }
        __syncthreads();

        // ---- online softmax (64 threads); causal mask; P -> fp16 sPh ----
        if (tid < 64) {
            int row = tid;
            int spos = qs + (row >> 4);
            float* pr = sP + row * 36;
            float v[32];
            float mo = pr[32], mx = mo;
#pragma unroll
            for (int j = 0; j < 32; j++) {
                float x = pr[j];
                if (t0 + j > spos) x = -1.0e30f;
                v[j] = x;
                mx = fmaxf(mx, x);
            }
            float al = __expf(mo - mx);
            float sum = 0.f;
#pragma unroll
            for (int j = 0; j < 32; j++) {
                v[j] = __expf(v[j] - mx);
                sum += v[j];
            }
#pragma unroll
            for (int jw = 0; jw < 16; jw++) {
                __half2 h = __floats2half2_rn(v[2 * jw], v[2 * jw + 1]);
                sPh[row * 20 + jw] = *(uint32_t*)&h;
            }
            pr[32] = mx;
            pr[33] = pr[33] * al + sum;
            pr[34] = al;
        }
        __syncthreads();

        // ---- PV (fp16): all 8 warps, 64 rows x 64 V-cols each ----
        {
            float al0[4], al1[4];
#pragma unroll
            for (int rg = 0; rg < 4; rg++) {
                al0[rg] = sP[(rg * 16 + gid) * 36 + 34];
                al1[rg] = sP[(rg * 16 + gid + 8) * 36 + 34];
            }
#pragma unroll
            for (int rg = 0; rg < 4; rg++)
#pragma unroll
                for (int j = 0; j < 8; j++) {
                    oacc[rg][j][0] *= al0[rg]; oacc[rg][j][1] *= al0[rg];
                    oacc[rg][j][2] *= al1[rg]; oacc[rg][j][3] *= al1[rg];
                }
#pragma unroll
            for (int kk = 0; kk < 2; kk++) {
                int kc = kk * 8;
                uint32_t A0[4], A1[4], A2[4], A3[4];
#pragma unroll
                for (int rg = 0; rg < 4; rg++) {
                    A0[rg] = sPh[(rg * 16 + gid) * 20 + kc + tig];
                    A1[rg] = sPh[(rg * 16 + gid + 8) * 20 + kc + tig];
                    A2[rg] = sPh[(rg * 16 + gid) * 20 + kc + tig + 4];
                    A3[rg] = sPh[(rg * 16 + gid + 8) * 20 + kc + tig + 4];
                }
#pragma unroll
                for (int j = 0; j < 8; j++) {
                    int col = w * 64 + j * 8 + gid;
                    uint32_t b0 = sv[col * 36 + kc + tig];
                    uint32_t b1 = sv[col * 36 + kc + tig + 4];
#pragma unroll
                    for (int rg = 0; rg < 4; rg++)
                        mma_f16(oacc[rg][j], A0[rg], A1[rg], A2[rg], A3[rg], b0, b1);
                }
            }
        }
        __syncthreads();   // PV done -> safe to overwrite sk/sv

        if (kt + 1 < ntk) {
            int tn = t0 + 32;
            for (int c = tid; c < 4352; c += 256) {
                if (c < 2304) {
                    int r = c / 72, ch = c - r * 72;
                    CPA16(sku + (r * 300 + 4 * ch) * 4, &kw[(long)(bS + tn + r) * 288 + 4 * ch]);
                } else {
                    int c2 = c - 2304;
                    int d = c2 >> 2, ch = c2 & 3;
                    CPA16(svu + (d * 36 + 4 * ch) * 4,
                          &vw[((long)b * RK + d) * (S_ / 2) + (tn >> 1) + 4 * ch]);
                }
            }
        }
        CPCOMMIT();
    }

    // ---- epilogue: normalize + write raw fp32 g_ol ----
#pragma unroll
    for (int rg = 0; rg < 4; rg++) {
        float l0 = 1.f / sP[(rg * 16 + gid) * 36 + 33];
        float l1 = 1.f / sP[(rg * 16 + gid + 8) * 36 + 33];
        long base = ((long)(bS + qs + rg)) * OLROW;
        float* o0 = g_ol + base + (long)gid * RK + w * 64;
        float* o1 = g_ol + base + (long)(gid + 8) * RK + w * 64;
#pragma unroll
        for (int j = 0; j < 8; j++) {
            int col = j * 8 + 2 * tig;
            *(float2*)&o0[col] = make_float2(oacc[rg][j][0] * l0, oacc[rg][j][1] * l0);
            *(float2*)&o1[col] = make_float2(oacc[rg][j][2] * l1, oacc[rg][j][3] * l1);
        }
    }
}

// ---------------- launch ----------------
extern "C" void kernel_launch(void* const* d_in, const int* in_sizes, int n_in,
                              void* d_out, int out_size)
{
    const float* x      = (const float*)d_in[0];
    const float* freqs  = (const float*)d_in[1];
    // d_in[2] = mask (causal handled analytically)
    const float* wq_w   = (const float*)d_in[3];
    const float* wq_b   = (const float*)d_in[4];
    const float* wkva_w = (const float*)d_in[5];
    const float* wkva_b = (const float*)d_in[6];
    const float* knw    = (const float*)d_in[7];
    const float* wkvb   = (const float*)d_in[8];
    const float* wo_w   = (const float*)d_in[9];
    const float* wo_b   = (const float*)d_in[10];
    float* out = (float*)d_out;

    void *vq, *vqfh, *vkv, *vol, *vov;
    cudaGetSymbolAddress(&vq,   g_q);
    cudaGetSymbolAddress(&vqfh, g_qfh);
    cudaGetSymbolAddress(&vkv,  g_kvt);
    cudaGetSymbolAddress(&vol,  g_ol);
    cudaGetSymbolAddress(&vov,  g_ov);
    const float* pq  = (const float*)vq;
    const float* pol = (const float*)vol;
    const float* pov = (const float*)vov;

    cudaFuncSetAttribute(flash_tc, cudaFuncAttributeMaxDynamicSharedMemorySize, FLASH_SMEM);
    cudaFuncSetAttribute(gemm_bs<true, true, 0>,
                         cudaFuncAttributeMaxDynamicSharedMemorySize, GEMM_SMEM);
    cudaFuncSetAttribute(gemm_bs<false, false, 1>,
                         cudaFuncAttributeMaxDynamicSharedMemorySize, GEMM_SMEM);
    cudaFuncSetAttribute(gemm_bs<true, false, 0>,
                         cudaFuncAttributeMaxDynamicSharedMemorySize, GEMM_SMEM);

    // 1) kv = x @ wkv_a^T + b : (4096, 576) raw fp32
    gemm_bs<true, true, 0><<<dim3(CD / 64, BS / 128, 1), 256, GEMM_SMEM>>>(
        D_, x, D_, 0, wkva_w, D_, 0, vkv, CD, 0, wkva_b, 1.f);

    // 2) rmsnorm + rope K -> g_kfh (fp16); transpose V -> g_kvT (fp16)
    kv_post<<<BS, 128>>>(freqs, knw);
    v_transpose<<<dim3(RK / 32, S_ / 32, B_), 256>>>();

    // 3) q = x @ wq^T + b : (4096, 3072) raw fp32
    gemm_bs<true, true, 0><<<dim3(QBROW / 64, BS / 128, 1), 256, GEMM_SMEM>>>(
        D_, x, D_, 0, wq_w, D_, 0, vq, QBROW, 0, wq_b, 1.f);

    // 4) rope q_pe (scaled, fp16) -> g_qfh[..., 512:576]
    q_rope<<<BS, 512>>>(freqs);

    // 5) q_absorbed per head: q_nope @ wkv_b_nope (K,N), scaled, fp16 out -> g_qfh
    gemm_bs<false, false, 1><<<dim3(RK / 64, BS / 128, H_), 256, GEMM_SMEM>>>(
        NOPE_, pq, QBROW, QK_HD,
        wkvb, RK, (long)(NOPE_ + V_HD) * RK,
        vqfh, H_ * CD, CD, nullptr, SCALE_);

    // 6) causal flash MQA -> g_ol (raw fp32)
    flash_tc<<<dim3(S_ / 4, B_), 256, FLASH_SMEM>>>();

    // 7) per-head V up-projection: o_lat @ wkv_b_v^T -> g_ov (raw fp32)
    gemm_bs<true, false, 0><<<dim3(V_HD / 64, BS / 128, H_), 256, GEMM_SMEM>>>(
        RK, pol, OLROW, RK,
        wkvb + (long)NOPE_ * RK, RK, (long)(NOPE_ + V_HD) * RK,
        vov, OVROW, V_HD, nullptr, 1.f);

    // 8) final: g_ov @ wo^T + wo_b -> out (fp32)
    gemm_bs<true, true, 0><<<dim3(D_ / 64, BS / 128, 1), 256, GEMM_SMEM>>>(
        OVROW, pov, OVROW, 0, wo_w, D_, 0, out, D_, 0, wo_b, 1.f);
}